// round 8
// baseline (speedup 1.0000x reference)
#include <cuda_runtime.h>
#include <cuda_fp16.h>
#include <math.h>
#include <stdint.h>

#define LL 16384
#define DD 1024
#define AA 1024

// ---------------- device scratch (static: allocation-free) ----------------
__device__ __half g_h16[LL * DD];  // h fp16 (32 MB)
__device__ __half g_w16[AA * DD];  // W1 fp16 (2 MB)
__device__ float g_c[AA];
__device__ float g_beta[LL];
__device__ float g_red[2];         // [0]=max, [1]=sum(exp)

// ---------------- PTX helpers (arch-neutral: sm_80+ features only) --------
__device__ __forceinline__ uint32_t smem_u32(const void* p){
    uint32_t a;
    asm("{ .reg .u64 t; cvta.to.shared.u64 t, %1; cvt.u32.u64 %0, t; }" : "=r"(a) : "l"(p));
    return a;
}
__device__ __forceinline__ void cp16(uint32_t dst, const void* src){
    asm volatile("cp.async.cg.shared.global [%0], [%1], 16;" :: "r"(dst), "l"(src) : "memory");
}
__device__ __forceinline__ void cp_commit(){
    asm volatile("cp.async.commit_group;" ::: "memory");
}
template<int N>
__device__ __forceinline__ void cp_wait(){
    asm volatile("cp.async.wait_group %0;" :: "n"(N) : "memory");
}
__device__ __forceinline__ void ldm4(uint32_t* r, uint32_t addr){
    asm volatile("ldmatrix.sync.aligned.m8n8.x4.shared.b16 {%0,%1,%2,%3}, [%4];"
        : "=r"(r[0]), "=r"(r[1]), "=r"(r[2]), "=r"(r[3]) : "r"(addr));
}
__device__ __forceinline__ void mma16816(float* d, const uint32_t* a,
                                         uint32_t b0, uint32_t b1){
    asm volatile(
        "mma.sync.aligned.m16n8k16.row.col.f32.f16.f16.f32 "
        "{%0,%1,%2,%3}, {%4,%5,%6,%7}, {%8,%9}, {%0,%1,%2,%3};"
        : "+f"(d[0]), "+f"(d[1]), "+f"(d[2]), "+f"(d[3])
        : "r"(a[0]), "r"(a[1]), "r"(a[2]), "r"(a[3]), "r"(b0), "r"(b1));
}

__device__ __forceinline__ float fast_tanh(float x){
    float e = __expf(-2.0f * fabsf(x));
    float t = __fdividef(1.0f - e, 1.0f + e);
    return copysignf(t, x);
}

// ---------------- prep kernel: h->fp16, W1->fp16, beta=0, c = W2@ht + b -----
// grid 17536 x 256:
//   blocks [0, 16384)        : h conversion (one float4-group per thread)
//   blocks [16384, 17408)    : W1 conversion + beta zeroing
//   blocks [17408, 17536)    : compute_c (8 warps x 128 blocks = 1024 rows)
__global__ void prep_kernel(const float* __restrict__ h,
                            const float* __restrict__ W,
                            const float* __restrict__ ht,
                            const float* __restrict__ b){
    const int bx = blockIdx.x, tid = threadIdx.x;
    if (bx < 16384){
        int idx = bx * 256 + tid;
        float4 v = ((const float4*)h)[idx];
        union { __half e[4]; uint2 u; } H;
        H.e[0] = __float2half(v.x);
        H.e[1] = __float2half(v.y);
        H.e[2] = __float2half(v.z);
        H.e[3] = __float2half(v.w);
        ((uint2*)g_h16)[idx] = H.u;
    } else if (bx < 17408){
        int idx = (bx - 16384) * 256 + tid;
        if (idx < LL) g_beta[idx] = 0.f;
        int a = idx >> 8, kg = idx & 255;
        float4 v = ((const float4*)(W + (size_t)a * 2048))[kg];
        union { __half e[4]; uint2 u; } H;
        H.e[0] = __float2half(v.x);
        H.e[1] = __float2half(v.y);
        H.e[2] = __float2half(v.z);
        H.e[3] = __float2half(v.w);
        ((uint2*)g_w16)[idx] = H.u;
    } else {
        int w = tid >> 5, lane = tid & 31;
        int a = (bx - 17408) * 8 + w;
        const float* Wr = W + (size_t)a * 2048 + 1024;
        float s = 0.f;
        #pragma unroll 4
        for (int k = lane; k < 1024; k += 32) s += Wr[k] * ht[k];
        #pragma unroll
        for (int o = 16; o; o >>= 1) s += __shfl_xor_sync(0xffffffffu, s, o);
        if (lane == 0) g_c[a] = s + b[a];
    }
}

// ---------------- kernel B: single fp16 product mma.sync GEMM --------------
// y = A16 * W16^T. CTA tile 128x128, 128 threads (4 warps, 2m x 2n),
// warp tile 64x64 (32 LDSM : 128 HMMA per warp-stage).
// K=64 per stage, 3-stage cp.async pipeline, 2 CTAs/SM.
// smem row stride 72 halves (144B) -> conflict-free ldmatrix.
// Stage layout (bytes): [A 18432][W 18432] = 36864, x3 stages.
#define RSTRIDE  72
#define BUFB     18432
#define STAGEB   36864
#define NSTAGE   3
#define KSTAGES  16            // 1024 / 64
#define DYN_SMEM (NSTAGE * STAGEB)

__device__ __forceinline__ void load_stage(uint32_t sb, int slot, int m_base, int n_base,
                                           int k0, int tid){
    uint32_t st  = sb + (uint32_t)slot * STAGEB;
    const int row = tid;                      // 0..127
    #pragma unroll
    for (int j = 0; j < 8; ++j){
        int col = j * 8;
        uint32_t doff = (uint32_t)((row * RSTRIDE + col) * 2);
        cp16(st + doff,        g_h16 + (size_t)(m_base + row) * DD + k0 + col);
        cp16(st + BUFB + doff, g_w16 + (size_t)(n_base + row) * DD + k0 + col);
    }
    cp_commit();
}

__global__ __launch_bounds__(128, 2)
void beta_mma_kernel(const float* __restrict__ u){
    extern __shared__ char dyn_sm[];
    __shared__ float cs[128], us[128];

    const int tid  = threadIdx.x;
    const int lane = tid & 31;
    const int wid  = tid >> 5;         // 0..3
    const int warp_m = wid & 1;        // 2 warps along m (64 rows each)
    const int warp_n = wid >> 1;       // 2 warps along n (64 cols each)
    const int m_base = blockIdx.x * 128;
    const int n_base = blockIdx.y * 128;
    const uint32_t sb = smem_u32(dyn_sm);

    cs[tid] = g_c[n_base + tid];
    us[tid] = u[n_base + tid];

    float acc[4][8][4];
    #pragma unroll
    for (int im = 0; im < 4; ++im)
        #pragma unroll
        for (int j = 0; j < 8; ++j)
            #pragma unroll
            for (int p = 0; p < 4; ++p) acc[im][j][p] = 0.f;

    load_stage(sb, 0, m_base, n_base, 0,  tid);
    load_stage(sb, 1, m_base, n_base, 64, tid);

    const int lr = lane & 15;
    const int lq = ((lane >> 4) & 1) * 8;

    int s = 0, sl = 2;                   // consume slot, next-fill slot
    for (int kt = 0; kt < KSTAGES; ++kt){
        cp_wait<1>();
        __syncthreads();

        if (kt + 2 < KSTAGES)
            load_stage(sb, sl, m_base, n_base, (kt + 2) * 64, tid);
        else
            cp_commit();   // keep wait_group bookkeeping uniform

        uint32_t st = sb + (uint32_t)s * STAGEB;
        #pragma unroll
        for (int half = 0; half < 4; ++half){
            const uint32_t col = lq + half * 16;
            uint32_t aF[4][4], bW[4][4];
            #pragma unroll
            for (int im = 0; im < 4; ++im){
                uint32_t off = (uint32_t)(((warp_m * 64 + im * 16 + lr) * RSTRIDE + col) * 2);
                ldm4(aF[im], st + off);
            }
            #pragma unroll
            for (int t = 0; t < 4; ++t){
                uint32_t off = (uint32_t)(((warp_n * 64 + t * 16 + lr) * RSTRIDE + col) * 2);
                ldm4(bW[t], st + BUFB + off);
            }
            #pragma unroll
            for (int im = 0; im < 4; ++im)
                #pragma unroll
                for (int i8 = 0; i8 < 8; ++i8){
                    const int t = i8 >> 1, hf = i8 & 1;
                    mma16816(acc[im][i8], aF[im], bW[t][hf], bW[t][hf + 2]);
                }
        }

        s  = (s  == NSTAGE - 1) ? 0 : s + 1;
        sl = (sl == NSTAGE - 1) ? 0 : sl + 1;
    }

    // epilogue: tanh(y + c) * u, reduce over n, atomic into g_beta
    #pragma unroll
    for (int im = 0; im < 4; ++im){
        #pragma unroll
        for (int rh = 0; rh < 2; ++rh){
            float p = 0.f;
            #pragma unroll
            for (int i8 = 0; i8 < 8; ++i8){
                int n = warp_n * 64 + i8 * 8 + 2 * (lane & 3);
                float v0 = acc[im][i8][rh * 2 + 0];
                float v1 = acc[im][i8][rh * 2 + 1];
                p += fast_tanh(v0 + cs[n])     * us[n];
                p += fast_tanh(v1 + cs[n + 1]) * us[n + 1];
            }
            p += __shfl_xor_sync(0xffffffffu, p, 1);
            p += __shfl_xor_sync(0xffffffffu, p, 2);
            if ((lane & 3) == 0){
                int row = m_base + warp_m * 64 + im * 16 + rh * 8 + (lane >> 2);
                atomicAdd(&g_beta[row], p);
            }
        }
    }
}

// ---------------- kernel C: softmax reductions + zero output ----------------
__global__ void softmax_kernel(float* __restrict__ out){
    __shared__ float red[32];
    const int tid = threadIdx.x;   // 1024 threads
    float mx = -3.0e38f;
    for (int i = tid; i < LL; i += 1024) mx = fmaxf(mx, g_beta[i]);
    #pragma unroll
    for (int o = 16; o; o >>= 1) mx = fmaxf(mx, __shfl_xor_sync(0xffffffffu, mx, o));
    if ((tid & 31) == 0) red[tid >> 5] = mx;
    __syncthreads();
    if (tid < 32){
        float v = red[tid];
        #pragma unroll
        for (int o = 16; o; o >>= 1) v = fmaxf(v, __shfl_xor_sync(0xffffffffu, v, o));
        if (tid == 0) red[0] = v;
    }
    __syncthreads();
    mx = red[0];
    __syncthreads();

    float s = 0.f;
    for (int i = tid; i < LL; i += 1024) s += __expf(g_beta[i] - mx);
    #pragma unroll
    for (int o = 16; o; o >>= 1) s += __shfl_xor_sync(0xffffffffu, s, o);
    if ((tid & 31) == 0) red[tid >> 5] = s;
    __syncthreads();
    if (tid < 32){
        float v = red[tid];
        #pragma unroll
        for (int o = 16; o; o >>= 1) v += __shfl_xor_sync(0xffffffffu, v, o);
        if (tid == 0){ g_red[0] = mx; g_red[1] = v; }
    }
    out[tid] = 0.f;
}

// ---------------- kernel D: s[d] = sum_i alpha_i * h[i][d], sparse ----------
// Near-one-hot softmax: any row with beta - max < -30 has alpha < 9.4e-14;
// the total dropped mass is < 16384 * 9.4e-14 ~ 1.5e-9 of Z (since the max
// term alone contributes exp(0)=1 to Z). Blocks whose 128 rows are all below
// the threshold exit before touching h.
__global__ __launch_bounds__(256)
void wsum_kernel(const float* __restrict__ h, float* __restrict__ out){
    __shared__ float wsm[128];
    __shared__ int alive;
    const int tid = threadIdx.x;
    const int i0 = blockIdx.y * 128;     // 128 row blocks
    if (tid == 0) alive = 0;
    __syncthreads();

    const float mx = g_red[0];
    const float invZ = 1.0f / g_red[1];
    if (tid < 128){
        float bv = g_beta[i0 + tid] - mx;
        if (bv > -30.f) alive = 1;
        wsm[tid] = __expf(bv) * invZ;
    }
    __syncthreads();
    if (!alive) return;

    const int d = blockIdx.x * 256 + tid;   // 4 col blocks
    float acc = 0.f;
    #pragma unroll 4
    for (int i = 0; i < 128; ++i)
        acc += wsm[i] * h[(size_t)(i0 + i) * 1024 + d];
    atomicAdd(&out[d], acc);
}

// ---------------- launch ----------------
extern "C" void kernel_launch(void* const* d_in, const int* in_sizes, int n_in,
                              void* d_out, int out_size){
    const float* h_i   = (const float*)d_in[0];
    const float* h_t   = (const float*)d_in[1];
    const float* W_att = (const float*)d_in[2];
    const float* b_att = (const float*)d_in[3];
    const float* u     = (const float*)d_in[4];
    float* out = (float*)d_out;

    cudaFuncSetAttribute(beta_mma_kernel,
                         cudaFuncAttributeMaxDynamicSharedMemorySize, DYN_SMEM);

    prep_kernel<<<17536, 256>>>(h_i, W_att, h_t, b_att);
    beta_mma_kernel<<<dim3(128, 8), 128, DYN_SMEM>>>(u);
    softmax_kernel<<<1, 1024>>>(out);
    wsum_kernel<<<dim3(4, 128), 256>>>(h_i, out);
}

// round 9
// speedup vs baseline: 1.2269x; 1.2269x over previous
#include <cuda_runtime.h>
#include <cuda_fp16.h>
#include <math.h>
#include <stdint.h>

#define LL 16384
#define DD 1024
#define AA 1024

// ---------------- device scratch (static: allocation-free) ----------------
__device__ __half g_h16[LL * DD];  // h fp16 (32 MB)
__device__ __half g_w16[AA * DD];  // W1 fp16 (2 MB)
__device__ float g_c[AA];
__device__ float g_beta[LL];
__device__ float g_red[2];         // [0]=max, [1]=sum(exp)

// ---------------- PTX helpers (arch-neutral: sm_80+ features only) --------
__device__ __forceinline__ uint32_t smem_u32(const void* p){
    uint32_t a;
    asm("{ .reg .u64 t; cvta.to.shared.u64 t, %1; cvt.u32.u64 %0, t; }" : "=r"(a) : "l"(p));
    return a;
}
__device__ __forceinline__ void cp16(uint32_t dst, const void* src){
    asm volatile("cp.async.cg.shared.global [%0], [%1], 16;" :: "r"(dst), "l"(src) : "memory");
}
__device__ __forceinline__ void cp_commit(){
    asm volatile("cp.async.commit_group;" ::: "memory");
}
template<int N>
__device__ __forceinline__ void cp_wait(){
    asm volatile("cp.async.wait_group %0;" :: "n"(N) : "memory");
}
__device__ __forceinline__ void ldm4(uint32_t* r, uint32_t addr){
    asm volatile("ldmatrix.sync.aligned.m8n8.x4.shared.b16 {%0,%1,%2,%3}, [%4];"
        : "=r"(r[0]), "=r"(r[1]), "=r"(r[2]), "=r"(r[3]) : "r"(addr));
}
__device__ __forceinline__ void mma16816(float* d, const uint32_t* a,
                                         uint32_t b0, uint32_t b1){
    asm volatile(
        "mma.sync.aligned.m16n8k16.row.col.f32.f16.f16.f32 "
        "{%0,%1,%2,%3}, {%4,%5,%6,%7}, {%8,%9}, {%0,%1,%2,%3};"
        : "+f"(d[0]), "+f"(d[1]), "+f"(d[2]), "+f"(d[3])
        : "r"(a[0]), "r"(a[1]), "r"(a[2]), "r"(a[3]), "r"(b0), "r"(b1));
}

__device__ __forceinline__ float fast_tanh(float x){
    float e = __expf(-2.0f * fabsf(x));
    float t = __fdividef(1.0f - e, 1.0f + e);
    return copysignf(t, x);
}

// ---------------- prep kernel: h->fp16, W1->fp16, beta=0, c = W2@ht + b -----
// grid 17536 x 256:
//   blocks [0, 16384)        : h conversion (one float4-group per thread)
//   blocks [16384, 17408)    : W1 conversion + beta zeroing
//   blocks [17408, 17536)    : compute_c (8 warps x 128 blocks = 1024 rows)
__global__ void prep_kernel(const float* __restrict__ h,
                            const float* __restrict__ W,
                            const float* __restrict__ ht,
                            const float* __restrict__ b){
    const int bx = blockIdx.x, tid = threadIdx.x;
    if (bx < 16384){
        int idx = bx * 256 + tid;
        float4 v = ((const float4*)h)[idx];
        union { __half e[4]; uint2 u; } H;
        H.e[0] = __float2half(v.x);
        H.e[1] = __float2half(v.y);
        H.e[2] = __float2half(v.z);
        H.e[3] = __float2half(v.w);
        ((uint2*)g_h16)[idx] = H.u;
    } else if (bx < 17408){
        int idx = (bx - 16384) * 256 + tid;
        if (idx < LL) g_beta[idx] = 0.f;
        int a = idx >> 8, kg = idx & 255;
        float4 v = ((const float4*)(W + (size_t)a * 2048))[kg];
        union { __half e[4]; uint2 u; } H;
        H.e[0] = __float2half(v.x);
        H.e[1] = __float2half(v.y);
        H.e[2] = __float2half(v.z);
        H.e[3] = __float2half(v.w);
        ((uint2*)g_w16)[idx] = H.u;
    } else {
        int w = tid >> 5, lane = tid & 31;
        int a = (bx - 17408) * 8 + w;
        const float* Wr = W + (size_t)a * 2048 + 1024;
        float s = 0.f;
        #pragma unroll 4
        for (int k = lane; k < 1024; k += 32) s += Wr[k] * ht[k];
        #pragma unroll
        for (int o = 16; o; o >>= 1) s += __shfl_xor_sync(0xffffffffu, s, o);
        if (lane == 0) g_c[a] = s + b[a];
    }
}

// ---------------- kernel B: single fp16 product mma.sync GEMM --------------
// (R7 configuration — measured 155 us)
// y = A16 * W16^T. CTA tile 128x128, 256 threads (8 warps, 4m x 2n),
// warp tile 32x64. K=64 per stage, 3-stage cp.async pipeline, 2 CTAs/SM.
// smem row stride 72 halves (144B) -> conflict-free ldmatrix.
// Stage layout (bytes): [A 18432][W 18432] = 36864, x3 stages.
#define RSTRIDE  72
#define BUFB     18432
#define STAGEB   36864
#define NSTAGE   3
#define KSTAGES  16            // 1024 / 64
#define DYN_SMEM (NSTAGE * STAGEB)

__device__ __forceinline__ void load_stage(uint32_t sb, int slot, int m_base, int n_base,
                                           int k0, int tid){
    uint32_t st  = sb + (uint32_t)slot * STAGEB;
    int row = tid >> 1;                      // 0..127
    int cb  = (tid & 1) * 32;                // col base: 0 or 32
    #pragma unroll
    for (int j = 0; j < 4; ++j){
        int col = cb + j * 8;
        uint32_t doff = (uint32_t)((row * RSTRIDE + col) * 2);
        cp16(st + doff,        g_h16 + (size_t)(m_base + row) * DD + k0 + col);
        cp16(st + BUFB + doff, g_w16 + (size_t)(n_base + row) * DD + k0 + col);
    }
    cp_commit();
}

__global__ __launch_bounds__(256, 2)
void beta_mma_kernel(const float* __restrict__ u){
    extern __shared__ char dyn_sm[];
    __shared__ float cs[128], us[128];

    const int tid  = threadIdx.x;
    const int lane = tid & 31;
    const int wid  = tid >> 5;
    const int warp_m = wid & 3;        // 4 warps along m (32 rows each)
    const int warp_n = wid >> 2;       // 2 warps along n (64 cols each)
    const int m_base = blockIdx.x * 128;
    const int n_base = blockIdx.y * 128;
    const uint32_t sb = smem_u32(dyn_sm);

    if (tid < 128){ cs[tid] = g_c[n_base + tid]; us[tid] = u[n_base + tid]; }

    float acc[2][8][4];
    #pragma unroll
    for (int im = 0; im < 2; ++im)
        #pragma unroll
        for (int j = 0; j < 8; ++j)
            #pragma unroll
            for (int p = 0; p < 4; ++p) acc[im][j][p] = 0.f;

    load_stage(sb, 0, m_base, n_base, 0,  tid);
    load_stage(sb, 1, m_base, n_base, 64, tid);

    const int lr = lane & 15;
    const int lq = ((lane >> 4) & 1) * 8;

    int s = 0, sl = 2;                   // consume slot, next-fill slot
    for (int kt = 0; kt < KSTAGES; ++kt){
        cp_wait<1>();
        __syncthreads();

        if (kt + 2 < KSTAGES)
            load_stage(sb, sl, m_base, n_base, (kt + 2) * 64, tid);
        else
            cp_commit();   // keep wait_group bookkeeping uniform

        uint32_t st = sb + (uint32_t)s * STAGEB;
        #pragma unroll
        for (int half = 0; half < 4; ++half){
            const uint32_t col = lq + half * 16;
            uint32_t aF[2][4], bW[4][4];
            #pragma unroll
            for (int im = 0; im < 2; ++im){
                uint32_t off = (uint32_t)(((warp_m * 32 + im * 16 + lr) * RSTRIDE + col) * 2);
                ldm4(aF[im], st + off);
            }
            #pragma unroll
            for (int t = 0; t < 4; ++t){
                uint32_t off = (uint32_t)(((warp_n * 64 + t * 16 + lr) * RSTRIDE + col) * 2);
                ldm4(bW[t], st + BUFB + off);
            }
            #pragma unroll
            for (int im = 0; im < 2; ++im)
                #pragma unroll
                for (int i8 = 0; i8 < 8; ++i8){
                    const int t = i8 >> 1, hf = i8 & 1;
                    mma16816(acc[im][i8], aF[im], bW[t][hf], bW[t][hf + 2]);
                }
        }

        s  = (s  == NSTAGE - 1) ? 0 : s + 1;
        sl = (sl == NSTAGE - 1) ? 0 : sl + 1;
    }

    // epilogue: tanh(y + c) * u, reduce over n, atomic into g_beta
    #pragma unroll
    for (int im = 0; im < 2; ++im){
        #pragma unroll
        for (int rh = 0; rh < 2; ++rh){
            float p = 0.f;
            #pragma unroll
            for (int i8 = 0; i8 < 8; ++i8){
                int n = warp_n * 64 + i8 * 8 + 2 * (lane & 3);
                float v0 = acc[im][i8][rh * 2 + 0];
                float v1 = acc[im][i8][rh * 2 + 1];
                p += fast_tanh(v0 + cs[n])     * us[n];
                p += fast_tanh(v1 + cs[n + 1]) * us[n + 1];
            }
            p += __shfl_xor_sync(0xffffffffu, p, 1);
            p += __shfl_xor_sync(0xffffffffu, p, 2);
            if ((lane & 3) == 0){
                int row = m_base + warp_m * 32 + im * 16 + rh * 8 + (lane >> 2);
                atomicAdd(&g_beta[row], p);
            }
        }
    }
}

// ---------------- kernel C: softmax reductions + zero output ----------------
__global__ void softmax_kernel(float* __restrict__ out){
    __shared__ float red[32];
    const int tid = threadIdx.x;   // 1024 threads
    float mx = -3.0e38f;
    for (int i = tid; i < LL; i += 1024) mx = fmaxf(mx, g_beta[i]);
    #pragma unroll
    for (int o = 16; o; o >>= 1) mx = fmaxf(mx, __shfl_xor_sync(0xffffffffu, mx, o));
    if ((tid & 31) == 0) red[tid >> 5] = mx;
    __syncthreads();
    if (tid < 32){
        float v = red[tid];
        #pragma unroll
        for (int o = 16; o; o >>= 1) v = fmaxf(v, __shfl_xor_sync(0xffffffffu, v, o));
        if (tid == 0) red[0] = v;
    }
    __syncthreads();
    mx = red[0];
    __syncthreads();

    float s = 0.f;
    for (int i = tid; i < LL; i += 1024) s += __expf(g_beta[i] - mx);
    #pragma unroll
    for (int o = 16; o; o >>= 1) s += __shfl_xor_sync(0xffffffffu, s, o);
    if ((tid & 31) == 0) red[tid >> 5] = s;
    __syncthreads();
    if (tid < 32){
        float v = red[tid];
        #pragma unroll
        for (int o = 16; o; o >>= 1) v += __shfl_xor_sync(0xffffffffu, v, o);
        if (tid == 0){ g_red[0] = mx; g_red[1] = v; }
    }
    out[tid] = 0.f;
}

// ---------------- kernel D: s[d] = sum_i alpha_i * h[i][d] ------------------
// 256 blocks x 64 rows. float4 loads, 4 independent accumulators (MLP),
// early-exit for fully-negligible row blocks (validated safe: dropped mass
// < 16384 * exp(-30) of Z < 1.5e-9 relative).
__global__ __launch_bounds__(256)
void wsum_kernel(const float* __restrict__ h, float* __restrict__ out){
    __shared__ float wsm[64];
    __shared__ int alive;
    const int tid = threadIdx.x;
    const int i0 = blockIdx.x * 64;      // 256 row blocks
    if (tid == 0) alive = 0;
    __syncthreads();

    const float mx = g_red[0];
    const float invZ = 1.0f / g_red[1];
    if (tid < 64){
        float bv = g_beta[i0 + tid] - mx;
        if (bv > -30.f) alive = 1;
        wsm[tid] = __expf(bv) * invZ;
    }
    __syncthreads();
    if (!alive) return;

    const float4* hp = (const float4*)(h + (size_t)i0 * 1024) + tid;  // col group
    float4 a0 = make_float4(0.f,0.f,0.f,0.f), a1 = a0, a2 = a0, a3 = a0;
    #pragma unroll
    for (int i = 0; i < 64; i += 4){
        float w0 = wsm[i], w1 = wsm[i+1], w2 = wsm[i+2], w3 = wsm[i+3];
        float4 v0 = hp[(size_t)(i+0) * 256];
        float4 v1 = hp[(size_t)(i+1) * 256];
        float4 v2 = hp[(size_t)(i+2) * 256];
        float4 v3 = hp[(size_t)(i+3) * 256];
        a0.x += w0*v0.x; a0.y += w0*v0.y; a0.z += w0*v0.z; a0.w += w0*v0.w;
        a1.x += w1*v1.x; a1.y += w1*v1.y; a1.z += w1*v1.z; a1.w += w1*v1.w;
        a2.x += w2*v2.x; a2.y += w2*v2.y; a2.z += w2*v2.z; a2.w += w2*v2.w;
        a3.x += w3*v3.x; a3.y += w3*v3.y; a3.z += w3*v3.z; a3.w += w3*v3.w;
    }
    float rx = (a0.x + a1.x) + (a2.x + a3.x);
    float ry = (a0.y + a1.y) + (a2.y + a3.y);
    float rz = (a0.z + a1.z) + (a2.z + a3.z);
    float rw = (a0.w + a1.w) + (a2.w + a3.w);
    atomicAdd(&out[tid * 4 + 0], rx);
    atomicAdd(&out[tid * 4 + 1], ry);
    atomicAdd(&out[tid * 4 + 2], rz);
    atomicAdd(&out[tid * 4 + 3], rw);
}

// ---------------- launch ----------------
extern "C" void kernel_launch(void* const* d_in, const int* in_sizes, int n_in,
                              void* d_out, int out_size){
    const float* h_i   = (const float*)d_in[0];
    const float* h_t   = (const float*)d_in[1];
    const float* W_att = (const float*)d_in[2];
    const float* b_att = (const float*)d_in[3];
    const float* u     = (const float*)d_in[4];
    float* out = (float*)d_out;

    cudaFuncSetAttribute(beta_mma_kernel,
                         cudaFuncAttributeMaxDynamicSharedMemorySize, DYN_SMEM);

    prep_kernel<<<17536, 256>>>(h_i, W_att, h_t, b_att);
    beta_mma_kernel<<<dim3(128, 8), 256, DYN_SMEM>>>(u);
    softmax_kernel<<<1, 1024>>>(out);
    wsum_kernel<<<256, 256>>>(h_i, out);
}

// round 10
// speedup vs baseline: 1.2641x; 1.0304x over previous
#include <cuda_runtime.h>
#include <cuda_fp16.h>
#include <math.h>
#include <stdint.h>

#define LL 16384
#define DD 1024
#define AA 1024

// ---------------- device scratch (static: allocation-free) ----------------
__device__ __half g_h16[LL * DD];  // h fp16 (32 MB)
__device__ __half g_w16[AA * DD];  // W1 fp16 (2 MB)
__device__ float g_c[AA];
__device__ float g_beta[LL];
__device__ float g_red[2];         // [0]=max, [1]=sum(exp)

// ---------------- PTX helpers (arch-neutral: sm_80+ features only) --------
__device__ __forceinline__ uint32_t smem_u32(const void* p){
    uint32_t a;
    asm("{ .reg .u64 t; cvta.to.shared.u64 t, %1; cvt.u32.u64 %0, t; }" : "=r"(a) : "l"(p));
    return a;
}
__device__ __forceinline__ void cp16(uint32_t dst, const void* src){
    asm volatile("cp.async.cg.shared.global [%0], [%1], 16;" :: "r"(dst), "l"(src) : "memory");
}
__device__ __forceinline__ void cp_commit(){
    asm volatile("cp.async.commit_group;" ::: "memory");
}
template<int N>
__device__ __forceinline__ void cp_wait(){
    asm volatile("cp.async.wait_group %0;" :: "n"(N) : "memory");
}
__device__ __forceinline__ void ldm4(uint32_t* r, uint32_t addr){
    asm volatile("ldmatrix.sync.aligned.m8n8.x4.shared.b16 {%0,%1,%2,%3}, [%4];"
        : "=r"(r[0]), "=r"(r[1]), "=r"(r[2]), "=r"(r[3]) : "r"(addr));
}
__device__ __forceinline__ void mma16816(float* d, const uint32_t* a,
                                         uint32_t b0, uint32_t b1){
    asm volatile(
        "mma.sync.aligned.m16n8k16.row.col.f32.f16.f16.f32 "
        "{%0,%1,%2,%3}, {%4,%5,%6,%7}, {%8,%9}, {%0,%1,%2,%3};"
        : "+f"(d[0]), "+f"(d[1]), "+f"(d[2]), "+f"(d[3])
        : "r"(a[0]), "r"(a[1]), "r"(a[2]), "r"(a[3]), "r"(b0), "r"(b1));
}

__device__ __forceinline__ float fast_tanh(float x){
    float e = __expf(-2.0f * fabsf(x));
    float t = __fdividef(1.0f - e, 1.0f + e);
    return copysignf(t, x);
}

// ---------------- prep kernel: h->fp16, W1->fp16, beta=0, c = W2@ht + b -----
__global__ void prep_kernel(const float* __restrict__ h,
                            const float* __restrict__ W,
                            const float* __restrict__ ht,
                            const float* __restrict__ b){
    const int bx = blockIdx.x, tid = threadIdx.x;
    if (bx < 16384){
        int idx = bx * 256 + tid;
        float4 v = ((const float4*)h)[idx];
        union { __half e[4]; uint2 u; } H;
        H.e[0] = __float2half(v.x);
        H.e[1] = __float2half(v.y);
        H.e[2] = __float2half(v.z);
        H.e[3] = __float2half(v.w);
        ((uint2*)g_h16)[idx] = H.u;
    } else if (bx < 17408){
        int idx = (bx - 16384) * 256 + tid;
        if (idx < LL) g_beta[idx] = 0.f;
        int a = idx >> 8, kg = idx & 255;
        float4 v = ((const float4*)(W + (size_t)a * 2048))[kg];
        union { __half e[4]; uint2 u; } H;
        H.e[0] = __float2half(v.x);
        H.e[1] = __float2half(v.y);
        H.e[2] = __float2half(v.z);
        H.e[3] = __float2half(v.w);
        ((uint2*)g_w16)[idx] = H.u;
    } else {
        int w = tid >> 5, lane = tid & 31;
        int a = (bx - 17408) * 8 + w;
        const float* Wr = W + (size_t)a * 2048 + 1024;
        float s = 0.f;
        #pragma unroll 4
        for (int k = lane; k < 1024; k += 32) s += Wr[k] * ht[k];
        #pragma unroll
        for (int o = 16; o; o >>= 1) s += __shfl_xor_sync(0xffffffffu, s, o);
        if (lane == 0) g_c[a] = s + b[a];
    }
}

// ---------------- kernel B: single fp16 product mma.sync GEMM --------------
// y = A16 * W16^T. CTA tile 256x128, 512 threads (16 warps, 8m x 2n),
// warp tile 32x64. K=64 per stage, 3-stage cp.async pipeline, 1 CTA/SM.
// Rationale: kernel is LDGSTS-issue-bound; 256-row M tile halves B redundancy
// (total cp.async bytes 512MB -> 384MB).
// smem row stride 72 halves (144B) -> conflict-free ldmatrix.
// Stage layout (bytes): [A 36864][W 18432] = 55296, x3 stages = 162KB.
#define RSTRIDE  72
#define ABUF     36864
#define BBUF     18432
#define STAGEB   (ABUF + BBUF)
#define NSTAGE   3
#define KSTAGES  16            // 1024 / 64
#define DYN_SMEM (NSTAGE * STAGEB)

__device__ __forceinline__ void load_stage(uint32_t sb, int slot, int m_base, int n_base,
                                           int k0, int tid){
    uint32_t st = sb + (uint32_t)slot * STAGEB;
    {   // A: 256 rows x 64 cols, 4 cp16 per thread
        int row = tid >> 1;
        int cb  = (tid & 1) * 32;
        #pragma unroll
        for (int j = 0; j < 4; ++j){
            int col = cb + j * 8;
            uint32_t doff = (uint32_t)((row * RSTRIDE + col) * 2);
            cp16(st + doff, g_h16 + (size_t)(m_base + row) * DD + k0 + col);
        }
    }
    {   // B: 128 rows x 64 cols, 2 cp16 per thread
        int row = tid >> 2;
        int cb  = (tid & 3) * 16;
        #pragma unroll
        for (int j = 0; j < 2; ++j){
            int col = cb + j * 8;
            uint32_t doff = (uint32_t)((row * RSTRIDE + col) * 2);
            cp16(st + ABUF + doff, g_w16 + (size_t)(n_base + row) * DD + k0 + col);
        }
    }
    cp_commit();
}

__global__ __launch_bounds__(512, 1)
void beta_mma_kernel(const float* __restrict__ u){
    extern __shared__ char dyn_sm[];
    __shared__ float cs[128], us[128];

    const int tid  = threadIdx.x;
    const int lane = tid & 31;
    const int wid  = tid >> 5;         // 0..15
    const int warp_m = wid & 7;        // 8 warps along m (32 rows each)
    const int warp_n = wid >> 3;       // 2 warps along n (64 cols each)
    const int m_base = blockIdx.x * 256;
    const int n_base = blockIdx.y * 128;
    const uint32_t sb = smem_u32(dyn_sm);

    if (tid < 128){ cs[tid] = g_c[n_base + tid]; us[tid] = u[n_base + tid]; }

    float acc[2][8][4];
    #pragma unroll
    for (int im = 0; im < 2; ++im)
        #pragma unroll
        for (int j = 0; j < 8; ++j)
            #pragma unroll
            for (int p = 0; p < 4; ++p) acc[im][j][p] = 0.f;

    load_stage(sb, 0, m_base, n_base, 0,  tid);
    load_stage(sb, 1, m_base, n_base, 64, tid);

    const int lr = lane & 15;
    const int lq = ((lane >> 4) & 1) * 8;

    int s = 0, sl = 2;                   // consume slot, next-fill slot
    for (int kt = 0; kt < KSTAGES; ++kt){
        cp_wait<1>();
        __syncthreads();

        if (kt + 2 < KSTAGES)
            load_stage(sb, sl, m_base, n_base, (kt + 2) * 64, tid);
        else
            cp_commit();   // keep wait_group bookkeeping uniform

        uint32_t st = sb + (uint32_t)s * STAGEB;
        #pragma unroll
        for (int half = 0; half < 4; ++half){
            const uint32_t col = lq + half * 16;
            uint32_t aF[2][4], bW[4][4];
            #pragma unroll
            for (int im = 0; im < 2; ++im){
                uint32_t off = (uint32_t)(((warp_m * 32 + im * 16 + lr) * RSTRIDE + col) * 2);
                ldm4(aF[im], st + off);
            }
            #pragma unroll
            for (int t = 0; t < 4; ++t){
                uint32_t off = (uint32_t)(((warp_n * 64 + t * 16 + lr) * RSTRIDE + col) * 2);
                ldm4(bW[t], st + ABUF + off);
            }
            #pragma unroll
            for (int im = 0; im < 2; ++im)
                #pragma unroll
                for (int i8 = 0; i8 < 8; ++i8){
                    const int t = i8 >> 1, hf = i8 & 1;
                    mma16816(acc[im][i8], aF[im], bW[t][hf], bW[t][hf + 2]);
                }
        }

        s  = (s  == NSTAGE - 1) ? 0 : s + 1;
        sl = (sl == NSTAGE - 1) ? 0 : sl + 1;
    }

    // epilogue: tanh(y + c) * u, reduce over n, atomic into g_beta
    #pragma unroll
    for (int im = 0; im < 2; ++im){
        #pragma unroll
        for (int rh = 0; rh < 2; ++rh){
            float p = 0.f;
            #pragma unroll
            for (int i8 = 0; i8 < 8; ++i8){
                int n = warp_n * 64 + i8 * 8 + 2 * (lane & 3);
                float v0 = acc[im][i8][rh * 2 + 0];
                float v1 = acc[im][i8][rh * 2 + 1];
                p += fast_tanh(v0 + cs[n])     * us[n];
                p += fast_tanh(v1 + cs[n + 1]) * us[n + 1];
            }
            p += __shfl_xor_sync(0xffffffffu, p, 1);
            p += __shfl_xor_sync(0xffffffffu, p, 2);
            if ((lane & 3) == 0){
                int row = m_base + warp_m * 32 + im * 16 + rh * 8 + (lane >> 2);
                atomicAdd(&g_beta[row], p);
            }
        }
    }
}

// ---------------- kernel C: softmax reductions + zero output ----------------
__global__ void softmax_kernel(float* __restrict__ out){
    __shared__ float red[32];
    const int tid = threadIdx.x;   // 1024 threads
    float mx = -3.0e38f;
    for (int i = tid; i < LL; i += 1024) mx = fmaxf(mx, g_beta[i]);
    #pragma unroll
    for (int o = 16; o; o >>= 1) mx = fmaxf(mx, __shfl_xor_sync(0xffffffffu, mx, o));
    if ((tid & 31) == 0) red[tid >> 5] = mx;
    __syncthreads();
    if (tid < 32){
        float v = red[tid];
        #pragma unroll
        for (int o = 16; o; o >>= 1) v = fmaxf(v, __shfl_xor_sync(0xffffffffu, v, o));
        if (tid == 0) red[0] = v;
    }
    __syncthreads();
    mx = red[0];
    __syncthreads();

    float s = 0.f;
    for (int i = tid; i < LL; i += 1024) s += __expf(g_beta[i] - mx);
    #pragma unroll
    for (int o = 16; o; o >>= 1) s += __shfl_xor_sync(0xffffffffu, s, o);
    if ((tid & 31) == 0) red[tid >> 5] = s;
    __syncthreads();
    if (tid < 32){
        float v = red[tid];
        #pragma unroll
        for (int o = 16; o; o >>= 1) v += __shfl_xor_sync(0xffffffffu, v, o);
        if (tid == 0){ g_red[0] = mx; g_red[1] = v; }
    }
    out[tid] = 0.f;
}

// ---------------- kernel D: s[d] = sum_i alpha_i * h16[i][d] ----------------
// grid (4 col-quarters, 128 row-blocks) = 512 blocks, 256 threads.
// Thread (rg = tid>>5, c = tid&31): 16 rows (stride 8) x 8 halves at chunk c.
// smem reduction over 8 row-groups, then one atomicAdd per scalar column.
// Early-exit for fully-negligible row blocks (dropped mass < 1.5e-9 of Z).
__global__ __launch_bounds__(256)
void wsum_kernel(float* __restrict__ out){
    __shared__ float wsm[128];
    __shared__ float part[8 * 256];
    __shared__ int alive;
    const int tid = threadIdx.x;
    const int i0 = blockIdx.y * 128;
    if (tid == 0) alive = 0;
    __syncthreads();

    const float mx = g_red[0];
    const float invZ = 1.0f / g_red[1];
    if (tid < 128){
        float bv = g_beta[i0 + tid] - mx;
        if (bv > -30.f) alive = 1;
        wsm[tid] = __expf(bv) * invZ;
    }
    __syncthreads();
    if (!alive) return;

    const int c  = tid & 31;           // 8-half chunk within the 256-col quarter
    const int rg = tid >> 5;           // row group 0..7
    const size_t col0 = (size_t)blockIdx.x * 256 + c * 8;
    const uint4* hp = (const uint4*)(g_h16 + (size_t)i0 * 1024 + col0);

    float acc[8];
    #pragma unroll
    for (int k = 0; k < 8; ++k) acc[k] = 0.f;

    #pragma unroll 2
    for (int i = rg; i < 128; i += 8){
        uint4 v = hp[(size_t)i * 128];         // row stride = 1024 halves = 128 uint4
        float w = wsm[i];
        const __half2* h2 = (const __half2*)&v;
        #pragma unroll
        for (int q = 0; q < 4; ++q){
            float2 f = __half22float2(h2[q]);
            acc[2*q + 0] += w * f.x;
            acc[2*q + 1] += w * f.y;
        }
    }
    #pragma unroll
    for (int k = 0; k < 8; ++k) part[rg * 256 + c * 8 + k] = acc[k];
    __syncthreads();

    float sum = 0.f;
    #pragma unroll
    for (int rg2 = 0; rg2 < 8; ++rg2) sum += part[rg2 * 256 + tid];
    atomicAdd(&out[blockIdx.x * 256 + tid], sum);
}

// ---------------- launch ----------------
extern "C" void kernel_launch(void* const* d_in, const int* in_sizes, int n_in,
                              void* d_out, int out_size){
    const float* h_i   = (const float*)d_in[0];
    const float* h_t   = (const float*)d_in[1];
    const float* W_att = (const float*)d_in[2];
    const float* b_att = (const float*)d_in[3];
    const float* u     = (const float*)d_in[4];
    float* out = (float*)d_out;

    cudaFuncSetAttribute(beta_mma_kernel,
                         cudaFuncAttributeMaxDynamicSharedMemorySize, DYN_SMEM);

    prep_kernel<<<17536, 256>>>(h_i, W_att, h_t, b_att);
    beta_mma_kernel<<<dim3(64, 8), 512, DYN_SMEM>>>(u);
    softmax_kernel<<<1, 1024>>>(out);
    wsum_kernel<<<dim3(4, 128), 256>>>(out);
}

// round 11
// speedup vs baseline: 1.6198x; 1.2814x over previous
#include <cuda_runtime.h>
#include <cuda_fp16.h>
#include <math.h>
#include <stdint.h>

#define LL 16384
#define DD 1024
#define AA 1024

// ---------------- device scratch (static: allocation-free) ----------------
// A: 64 m-blocks x 16 k-chunks, tile 256x64 halves = 32KB, SW128-preswizzled
// B: 8  n-blocks x 16 k-chunks, tile 128x64 halves = 16KB, SW128-preswizzled
__device__ uint4 g_hA[2097152];    // 32 MB
__device__ uint4 g_wB[131072];     // 2 MB
__device__ __half g_h16[LL * DD];  // row-major h fp16 (for wsum) 32 MB
__device__ float g_c[AA];
__device__ float g_beta[LL];
__device__ float g_red[2];         // [0]=max, [1]=sum(exp)

// ---------------- PTX helpers ----------------
__device__ __forceinline__ uint32_t smem_u32(const void* p){
    uint32_t a;
    asm("{ .reg .u64 t; cvta.to.shared.u64 t, %1; cvt.u32.u64 %0, t; }" : "=r"(a) : "l"(p));
    return a;
}
__device__ __forceinline__ uint32_t swz128(uint32_t off){ return off ^ ((off >> 3) & 0x70u); }

__device__ __forceinline__ void mbar_init(uint32_t mbar, uint32_t cnt){
    asm volatile("mbarrier.init.shared.b64 [%0], %1;" :: "r"(mbar), "r"(cnt) : "memory");
}
__device__ __forceinline__ void mbar_expect_tx(uint32_t mbar, uint32_t bytes){
    asm volatile("mbarrier.arrive.expect_tx.shared.b64 _, [%0], %1;"
                 :: "r"(mbar), "r"(bytes) : "memory");
}
__device__ __forceinline__ void mbar_wait(uint32_t mbar, int parity){
    asm volatile(
        "{\n\t.reg .pred P1;\n\t"
        "LAB_WAIT_%=:\n\t"
        "mbarrier.try_wait.parity.acquire.cta.shared::cta.b64 P1, [%0], %1, 0x989680;\n\t"
        "@P1 bra.uni LAB_DONE_%=;\n\t"
        "bra.uni LAB_WAIT_%=;\n\t"
        "LAB_DONE_%=:\n\t}"
        :: "r"(mbar), "r"((uint32_t)parity) : "memory");
}
__device__ __forceinline__ void bulkcp(uint32_t dst, const void* src, uint32_t bytes,
                                       uint32_t mbar){
    asm volatile(
        "cp.async.bulk.shared::cta.global.mbarrier::complete_tx::bytes [%0], [%1], %2, [%3];"
        :: "r"(dst), "l"(src), "r"(bytes), "r"(mbar) : "memory");
}
__device__ __forceinline__ void ldm4(uint32_t* r, uint32_t addr){
    asm volatile("ldmatrix.sync.aligned.m8n8.x4.shared.b16 {%0,%1,%2,%3}, [%4];"
        : "=r"(r[0]), "=r"(r[1]), "=r"(r[2]), "=r"(r[3]) : "r"(addr));
}
__device__ __forceinline__ void mma16816(float* d, const uint32_t* a,
                                         uint32_t b0, uint32_t b1){
    asm volatile(
        "mma.sync.aligned.m16n8k16.row.col.f32.f16.f16.f32 "
        "{%0,%1,%2,%3}, {%4,%5,%6,%7}, {%8,%9}, {%0,%1,%2,%3};"
        : "+f"(d[0]), "+f"(d[1]), "+f"(d[2]), "+f"(d[3])
        : "r"(a[0]), "r"(a[1]), "r"(a[2]), "r"(a[3]), "r"(b0), "r"(b1));
}

__device__ __forceinline__ float fast_tanh(float x){
    float e = __expf(-2.0f * fabsf(x));
    float t = __fdividef(1.0f - e, 1.0f + e);
    return copysignf(t, x);
}

__device__ __forceinline__ uint4 cvt8(const float* src){
    union { __half e[8]; uint4 u; } H;
    #pragma unroll
    for (int q = 0; q < 8; ++q) H.e[q] = __float2half(src[q]);
    return H.u;
}

// ---------------- prep kernel --------------------------------------------
// blocks [0, 8192)     : h -> fp16 tiled+swizzled g_hA AND row-major g_h16
// blocks [8192, 8704)  : W1 -> fp16 tiled+swizzled g_wB
// blocks [8704, 8768)  : zero g_beta
// blocks [8768, 8896)  : c = W2 @ ht + b
__global__ void prep_kernel(const float* __restrict__ h,
                            const float* __restrict__ W,
                            const float* __restrict__ ht,
                            const float* __restrict__ b){
    const int bx = blockIdx.x, tid = threadIdx.x;
    if (bx < 8192){
        int t = bx * 256 + tid;          // 2M chunks of 8 halves
        int m = t >> 7, j = t & 127;
        int kc = j >> 3, jj = j & 7;
        float v[8];
        const float* src = h + (size_t)m * 1024 + kc * 64 + jj * 8;
        #pragma unroll
        for (int q = 0; q < 8; ++q) v[q] = src[q];
        uint4 u16 = cvt8(v);
        size_t doff = ((size_t)((m >> 8) * 16 + kc)) * 32768
                    + swz128((uint32_t)((m & 255) * 128 + jj * 16));
        *(uint4*)((char*)g_hA + doff) = u16;
        ((uint4*)g_h16)[(size_t)m * 128 + j] = u16;    // row-major copy for wsum
    } else if (bx < 8704){
        int t = (bx - 8192) * 256 + tid; // 131072 chunks
        int a = t >> 7, j = t & 127;
        int kc = j >> 3, jj = j & 7;
        float v[8];
        const float* src = W + (size_t)a * 2048 + kc * 64 + jj * 8;
        #pragma unroll
        for (int q = 0; q < 8; ++q) v[q] = src[q];
        uint4 u16 = cvt8(v);
        size_t doff = ((size_t)((a >> 7) * 16 + kc)) * 16384
                    + swz128((uint32_t)((a & 127) * 128 + jj * 16));
        *(uint4*)((char*)g_wB + doff) = u16;
    } else if (bx < 8768){
        int idx = (bx - 8704) * 256 + tid;
        g_beta[idx] = 0.f;
    } else {
        int w = tid >> 5, lane = tid & 31;
        int a = (bx - 8768) * 8 + w;
        const float* Wr = W + (size_t)a * 2048 + 1024;
        float s = 0.f;
        #pragma unroll 4
        for (int k = lane; k < 1024; k += 32) s += Wr[k] * ht[k];
        #pragma unroll
        for (int o = 16; o; o >>= 1) s += __shfl_xor_sync(0xffffffffu, s, o);
        if (lane == 0) g_c[a] = s + b[a];
    }
}

// ---------------- kernel B: bulk-copy pipelined fp16 mma.sync GEMM ---------
// CTA tile 256x128, 512 threads (16 warps, 8m x 2n), warp tile 32x64.
// K=64 per stage; per stage ONE thread issues 2 cp.async.bulk (48KB total)
// with mbarrier complete_tx. 3 stages = 144KB smem, 1 CTA/SM.
#define ATILE   32768
#define BTILE   16384
#define STAGEB  49152
#define NSTAGE  3
#define KSTAGES 16
#define DYN_SMEM (NSTAGE * STAGEB + 1024)

__global__ __launch_bounds__(512, 1)
void beta_mma_kernel(const float* __restrict__ u){
    extern __shared__ __align__(1024) char dyn_sm[];
    __shared__ float cs[128], us[128];
    __shared__ unsigned long long mbar[NSTAGE];

    const int tid  = threadIdx.x;
    const int lane = tid & 31;
    const int wid  = tid >> 5;         // 0..15
    const int warp_m = wid & 7;        // 8 warps along m (32 rows each)
    const int warp_n = wid >> 3;       // 2 warps along n (64 cols each)
    const int mb = blockIdx.x;         // 64 m-blocks
    const int nb = blockIdx.y;         // 8 n-blocks
    const uint32_t sb = (smem_u32(dyn_sm) + 1023u) & ~1023u;
    const uint32_t mb0 = smem_u32(&mbar[0]);
    const uint32_t mb1 = smem_u32(&mbar[1]);
    const uint32_t mb2 = smem_u32(&mbar[2]);

    if (tid < 128){ cs[tid] = g_c[nb * 128 + tid]; us[tid] = u[nb * 128 + tid]; }
    if (tid == 0){ mbar_init(mb0, 1); mbar_init(mb1, 1); mbar_init(mb2, 1); }
    __syncthreads();

    const char* srcA = (const char*)g_hA + (size_t)mb * 16 * ATILE;
    const char* srcB = (const char*)g_wB + (size_t)nb * 16 * BTILE;

    if (tid == 0){
        #pragma unroll
        for (int slot = 0; slot < 2; ++slot){
            uint32_t mba = slot ? mb1 : mb0;
            mbar_expect_tx(mba, STAGEB);
            bulkcp(sb + slot * STAGEB,         srcA + (size_t)slot * ATILE, ATILE, mba);
            bulkcp(sb + slot * STAGEB + ATILE, srcB + (size_t)slot * BTILE, BTILE, mba);
        }
    }

    float acc[2][8][4];
    #pragma unroll
    for (int im = 0; im < 2; ++im)
        #pragma unroll
        for (int j = 0; j < 8; ++j)
            #pragma unroll
            for (int p = 0; p < 4; ++p) acc[im][j][p] = 0.f;

    const int lr = lane & 15;
    const uint32_t cb0 = ((lane >> 4) & 1) * 16;   // byte offset within 128B row

    int s = 0, sl = 2;
    int p0 = 0, p1 = 0, p2 = 0;
    for (int kt = 0; kt < KSTAGES; ++kt){
        if (s == 0){ mbar_wait(mb0, p0); p0 ^= 1; }
        else if (s == 1){ mbar_wait(mb1, p1); p1 ^= 1; }
        else { mbar_wait(mb2, p2); p2 ^= 1; }
        __syncthreads();   // all warps past previous use of slot sl

        if (tid == 0 && kt + 2 < KSTAGES){
            int kc = kt + 2;
            uint32_t mba = (sl == 0) ? mb0 : (sl == 1) ? mb1 : mb2;
            mbar_expect_tx(mba, STAGEB);
            bulkcp(sb + sl * STAGEB,         srcA + (size_t)kc * ATILE, ATILE, mba);
            bulkcp(sb + sl * STAGEB + ATILE, srcB + (size_t)kc * BTILE, BTILE, mba);
        }

        uint32_t st = sb + (uint32_t)s * STAGEB;
        #pragma unroll
        for (int half = 0; half < 4; ++half){
            const uint32_t cbyte = cb0 + half * 32;
            uint32_t aF[2][4], bW[4][4];
            #pragma unroll
            for (int im = 0; im < 2; ++im){
                uint32_t row = (uint32_t)(warp_m * 32 + im * 16 + lr);
                ldm4(aF[im], st + swz128(row * 128 + cbyte));
            }
            #pragma unroll
            for (int t = 0; t < 4; ++t){
                uint32_t row = (uint32_t)(warp_n * 64 + t * 16 + lr);
                ldm4(bW[t], st + ATILE + swz128(row * 128 + cbyte));
            }
            #pragma unroll
            for (int im = 0; im < 2; ++im)
                #pragma unroll
                for (int i8 = 0; i8 < 8; ++i8){
                    const int t = i8 >> 1, hf = i8 & 1;
                    mma16816(acc[im][i8], aF[im], bW[t][hf], bW[t][hf + 2]);
                }
        }

        s  = (s  == NSTAGE - 1) ? 0 : s + 1;
        sl = (sl == NSTAGE - 1) ? 0 : sl + 1;
    }

    // epilogue: tanh(y + c) * u, reduce over n, atomic into g_beta
    #pragma unroll
    for (int im = 0; im < 2; ++im){
        #pragma unroll
        for (int rh = 0; rh < 2; ++rh){
            float p = 0.f;
            #pragma unroll
            for (int i8 = 0; i8 < 8; ++i8){
                int n = warp_n * 64 + i8 * 8 + 2 * (lane & 3);
                float v0 = acc[im][i8][rh * 2 + 0];
                float v1 = acc[im][i8][rh * 2 + 1];
                p += fast_tanh(v0 + cs[n])     * us[n];
                p += fast_tanh(v1 + cs[n + 1]) * us[n + 1];
            }
            p += __shfl_xor_sync(0xffffffffu, p, 1);
            p += __shfl_xor_sync(0xffffffffu, p, 2);
            if ((lane & 3) == 0){
                int row = mb * 256 + warp_m * 32 + im * 16 + rh * 8 + (lane >> 2);
                atomicAdd(&g_beta[row], p);
            }
        }
    }
}

// ---------------- kernel C: softmax reductions + zero output ----------------
__global__ void softmax_kernel(float* __restrict__ out){
    __shared__ float red[32];
    const int tid = threadIdx.x;   // 1024 threads
    float mx = -3.0e38f;
    for (int i = tid; i < LL; i += 1024) mx = fmaxf(mx, g_beta[i]);
    #pragma unroll
    for (int o = 16; o; o >>= 1) mx = fmaxf(mx, __shfl_xor_sync(0xffffffffu, mx, o));
    if ((tid & 31) == 0) red[tid >> 5] = mx;
    __syncthreads();
    if (tid < 32){
        float v = red[tid];
        #pragma unroll
        for (int o = 16; o; o >>= 1) v = fmaxf(v, __shfl_xor_sync(0xffffffffu, v, o));
        if (tid == 0) red[0] = v;
    }
    __syncthreads();
    mx = red[0];
    __syncthreads();

    float s = 0.f;
    for (int i = tid; i < LL; i += 1024) s += __expf(g_beta[i] - mx);
    #pragma unroll
    for (int o = 16; o; o >>= 1) s += __shfl_xor_sync(0xffffffffu, s, o);
    if ((tid & 31) == 0) red[tid >> 5] = s;
    __syncthreads();
    if (tid < 32){
        float v = red[tid];
        #pragma unroll
        for (int o = 16; o; o >>= 1) v += __shfl_xor_sync(0xffffffffu, v, o);
        if (tid == 0){ g_red[0] = mx; g_red[1] = v; }
    }
    out[tid] = 0.f;
}

// ---------------- kernel D: s[d] = sum_i alpha_i * h16[i][d] ----------------
__global__ __launch_bounds__(256)
void wsum_kernel(float* __restrict__ out){
    __shared__ float wsm[128];
    __shared__ float part[8 * 256];
    __shared__ int alive;
    const int tid = threadIdx.x;
    const int i0 = blockIdx.y * 128;
    if (tid == 0) alive = 0;
    __syncthreads();

    const float mx = g_red[0];
    const float invZ = 1.0f / g_red[1];
    if (tid < 128){
        float bv = g_beta[i0 + tid] - mx;
        if (bv > -30.f) alive = 1;
        wsm[tid] = __expf(bv) * invZ;
    }
    __syncthreads();
    if (!alive) return;

    const int c  = tid & 31;
    const int rg = tid >> 5;
    const size_t col0 = (size_t)blockIdx.x * 256 + c * 8;
    const uint4* hp = (const uint4*)(g_h16 + (size_t)i0 * 1024 + col0);

    float acc[8];
    #pragma unroll
    for (int k = 0; k < 8; ++k) acc[k] = 0.f;

    #pragma unroll 2
    for (int i = rg; i < 128; i += 8){
        uint4 v = hp[(size_t)i * 128];
        float w = wsm[i];
        const __half2* h2 = (const __half2*)&v;
        #pragma unroll
        for (int q = 0; q < 4; ++q){
            float2 f = __half22float2(h2[q]);
            acc[2*q + 0] += w * f.x;
            acc[2*q + 1] += w * f.y;
        }
    }
    #pragma unroll
    for (int k = 0; k < 8; ++k) part[rg * 256 + c * 8 + k] = acc[k];
    __syncthreads();

    float sum = 0.f;
    #pragma unroll
    for (int rg2 = 0; rg2 < 8; ++rg2) sum += part[rg2 * 256 + tid];
    atomicAdd(&out[blockIdx.x * 256 + tid], sum);
}

// ---------------- launch ----------------
extern "C" void kernel_launch(void* const* d_in, const int* in_sizes, int n_in,
                              void* d_out, int out_size){
    const float* h_i   = (const float*)d_in[0];
    const float* h_t   = (const float*)d_in[1];
    const float* W_att = (const float*)d_in[2];
    const float* b_att = (const float*)d_in[3];
    const float* u     = (const float*)d_in[4];
    float* out = (float*)d_out;

    cudaFuncSetAttribute(beta_mma_kernel,
                         cudaFuncAttributeMaxDynamicSharedMemorySize, DYN_SMEM);

    prep_kernel<<<8896, 256>>>(h_i, W_att, h_t, b_att);
    beta_mma_kernel<<<dim3(64, 8), 512, DYN_SMEM>>>(u);
    softmax_kernel<<<1, 1024>>>(out);
    wsum_kernel<<<dim3(4, 128), 256>>>(out);
}

// round 12
// speedup vs baseline: 1.9389x; 1.1970x over previous
#include <cuda_runtime.h>
#include <cuda_fp16.h>
#include <math.h>
#include <stdint.h>

#define LL 16384
#define DD 1024
#define AA 1024

// ---------------- device scratch (static: allocation-free) ----------------
// A: 128 m-blocks x 16 k-chunks, tile 128x64 halves = 16KB, SW128-preswizzled
// B: 8   n-blocks x 16 k-chunks, tile 128x64 halves = 16KB, SW128-preswizzled
__device__ uint4 g_hA[2097152];    // 32 MB
__device__ uint4 g_wB[131072];     // 2 MB
__device__ float g_c[AA];
__device__ float g_beta[LL];
__device__ float g_red[2];         // [0]=max, [1]=sum(exp)

// ---------------- PTX helpers ----------------
__device__ __forceinline__ uint32_t smem_u32(const void* p){
    uint32_t a;
    asm("{ .reg .u64 t; cvta.to.shared.u64 t, %1; cvt.u32.u64 %0, t; }" : "=r"(a) : "l"(p));
    return a;
}
__device__ __forceinline__ uint32_t swz128(uint32_t off){ return off ^ ((off >> 3) & 0x70u); }

__device__ __forceinline__ void mbar_init(uint32_t mbar, uint32_t cnt){
    asm volatile("mbarrier.init.shared.b64 [%0], %1;" :: "r"(mbar), "r"(cnt) : "memory");
}
__device__ __forceinline__ void mbar_expect_tx(uint32_t mbar, uint32_t bytes){
    asm volatile("mbarrier.arrive.expect_tx.shared.b64 _, [%0], %1;"
                 :: "r"(mbar), "r"(bytes) : "memory");
}
__device__ __forceinline__ void mbar_wait(uint32_t mbar, int parity){
    asm volatile(
        "{\n\t.reg .pred P1;\n\t"
        "LAB_WAIT_%=:\n\t"
        "mbarrier.try_wait.parity.acquire.cta.shared::cta.b64 P1, [%0], %1, 0x989680;\n\t"
        "@P1 bra.uni LAB_DONE_%=;\n\t"
        "bra.uni LAB_WAIT_%=;\n\t"
        "LAB_DONE_%=:\n\t}"
        :: "r"(mbar), "r"((uint32_t)parity) : "memory");
}
__device__ __forceinline__ void bulkcp(uint32_t dst, const void* src, uint32_t bytes,
                                       uint32_t mbar){
    asm volatile(
        "cp.async.bulk.shared::cta.global.mbarrier::complete_tx::bytes [%0], [%1], %2, [%3];"
        :: "r"(dst), "l"(src), "r"(bytes), "r"(mbar) : "memory");
}
__device__ __forceinline__ void ldm4(uint32_t* r, uint32_t addr){
    asm volatile("ldmatrix.sync.aligned.m8n8.x4.shared.b16 {%0,%1,%2,%3}, [%4];"
        : "=r"(r[0]), "=r"(r[1]), "=r"(r[2]), "=r"(r[3]) : "r"(addr));
}
__device__ __forceinline__ void mma16816(float* d, const uint32_t* a,
                                         uint32_t b0, uint32_t b1){
    asm volatile(
        "mma.sync.aligned.m16n8k16.row.col.f32.f16.f16.f32 "
        "{%0,%1,%2,%3}, {%4,%5,%6,%7}, {%8,%9}, {%0,%1,%2,%3};"
        : "+f"(d[0]), "+f"(d[1]), "+f"(d[2]), "+f"(d[3])
        : "r"(a[0]), "r"(a[1]), "r"(a[2]), "r"(a[3]), "r"(b0), "r"(b1));
}

__device__ __forceinline__ float fast_tanh(float x){
    float e = __expf(-2.0f * fabsf(x));
    float t = __fdividef(1.0f - e, 1.0f + e);
    return copysignf(t, x);
}

__device__ __forceinline__ uint4 cvt8(const float* src){
    union { __half e[8]; uint4 u; } H;
    #pragma unroll
    for (int q = 0; q < 8; ++q) H.e[q] = __float2half(src[q]);
    return H.u;
}

// ---------------- prep kernel --------------------------------------------
// blocks [0, 8192)     : h -> fp16 tiled+swizzled g_hA (128x64 tiles)
// blocks [8192, 8704)  : W1 -> fp16 tiled+swizzled g_wB
// blocks [8704, 8768)  : zero g_beta
// blocks [8768, 8896)  : c = W2 @ ht + b
__global__ void prep_kernel(const float* __restrict__ h,
                            const float* __restrict__ W,
                            const float* __restrict__ ht,
                            const float* __restrict__ b){
    const int bx = blockIdx.x, tid = threadIdx.x;
    if (bx < 8192){
        int t = bx * 256 + tid;          // 2M chunks of 8 halves
        int m = t >> 7, j = t & 127;
        int kc = j >> 3, jj = j & 7;
        float v[8];
        const float* src = h + (size_t)m * 1024 + kc * 64 + jj * 8;
        #pragma unroll
        for (int q = 0; q < 8; ++q) v[q] = src[q];
        uint4 u16 = cvt8(v);
        size_t doff = ((size_t)((m >> 7) * 16 + kc)) * 16384
                    + swz128((uint32_t)((m & 127) * 128 + jj * 16));
        *(uint4*)((char*)g_hA + doff) = u16;
    } else if (bx < 8704){
        int t = (bx - 8192) * 256 + tid; // 131072 chunks
        int a = t >> 7, j = t & 127;
        int kc = j >> 3, jj = j & 7;
        float v[8];
        const float* src = W + (size_t)a * 2048 + kc * 64 + jj * 8;
        #pragma unroll
        for (int q = 0; q < 8; ++q) v[q] = src[q];
        uint4 u16 = cvt8(v);
        size_t doff = ((size_t)((a >> 7) * 16 + kc)) * 16384
                    + swz128((uint32_t)((a & 127) * 128 + jj * 16));
        *(uint4*)((char*)g_wB + doff) = u16;
    } else if (bx < 8768){
        int idx = (bx - 8704) * 256 + tid;
        g_beta[idx] = 0.f;
    } else {
        int w = tid >> 5, lane = tid & 31;
        int a = (bx - 8768) * 8 + w;
        const float* Wr = W + (size_t)a * 2048 + 1024;
        float s = 0.f;
        #pragma unroll 4
        for (int k = lane; k < 1024; k += 32) s += Wr[k] * ht[k];
        #pragma unroll
        for (int o = 16; o; o >>= 1) s += __shfl_xor_sync(0xffffffffu, s, o);
        if (lane == 0) g_c[a] = s + b[a];
    }
}

// ---------------- kernel B: bulk-copy pipelined fp16 mma.sync GEMM ---------
// CTA tile 128x128, 256 threads (8 warps, 4m x 2n), warp tile 32x64.
// K=64 per stage; ONE thread issues 2 cp.async.bulk (32KB) per stage with
// mbarrier complete_tx. 3 stages = 97KB smem -> 2 CTAs/SM (bubble overlap).
#define ATILE   16384
#define BTILE   16384
#define STAGEB  32768
#define NSTAGE  3
#define KSTAGES 16
#define DYN_SMEM (NSTAGE * STAGEB + 1024)

__global__ __launch_bounds__(256, 2)
void beta_mma_kernel(const float* __restrict__ u){
    extern __shared__ __align__(1024) char dyn_sm[];
    __shared__ float cs[128], us[128];
    __shared__ unsigned long long mbar[NSTAGE];

    const int tid  = threadIdx.x;
    const int lane = tid & 31;
    const int wid  = tid >> 5;         // 0..7
    const int warp_m = wid & 3;        // 4 warps along m (32 rows each)
    const int warp_n = wid >> 2;       // 2 warps along n (64 cols each)
    const int mb = blockIdx.x;         // 128 m-blocks
    const int nb = blockIdx.y;         // 8 n-blocks
    const uint32_t sb = (smem_u32(dyn_sm) + 1023u) & ~1023u;
    const uint32_t mb0 = smem_u32(&mbar[0]);
    const uint32_t mb1 = smem_u32(&mbar[1]);
    const uint32_t mb2 = smem_u32(&mbar[2]);

    if (tid < 128){ cs[tid] = g_c[nb * 128 + tid]; us[tid] = u[nb * 128 + tid]; }
    if (tid == 0){ mbar_init(mb0, 1); mbar_init(mb1, 1); mbar_init(mb2, 1); }
    __syncthreads();

    const char* srcA = (const char*)g_hA + (size_t)mb * 16 * ATILE;
    const char* srcB = (const char*)g_wB + (size_t)nb * 16 * BTILE;

    if (tid == 0){
        #pragma unroll
        for (int slot = 0; slot < 2; ++slot){
            uint32_t mba = slot ? mb1 : mb0;
            mbar_expect_tx(mba, STAGEB);
            bulkcp(sb + slot * STAGEB,         srcA + (size_t)slot * ATILE, ATILE, mba);
            bulkcp(sb + slot * STAGEB + ATILE, srcB + (size_t)slot * BTILE, BTILE, mba);
        }
    }

    float acc[2][8][4];
    #pragma unroll
    for (int im = 0; im < 2; ++im)
        #pragma unroll
        for (int j = 0; j < 8; ++j)
            #pragma unroll
            for (int p = 0; p < 4; ++p) acc[im][j][p] = 0.f;

    const int lr = lane & 15;
    const uint32_t cb0 = ((lane >> 4) & 1) * 16;   // byte offset within 128B row

    int s = 0, sl = 2;
    int p0 = 0, p1 = 0, p2 = 0;
    for (int kt = 0; kt < KSTAGES; ++kt){
        if (s == 0){ mbar_wait(mb0, p0); p0 ^= 1; }
        else if (s == 1){ mbar_wait(mb1, p1); p1 ^= 1; }
        else { mbar_wait(mb2, p2); p2 ^= 1; }
        __syncthreads();   // all warps past previous use of slot sl

        if (tid == 0 && kt + 2 < KSTAGES){
            int kc = kt + 2;
            uint32_t mba = (sl == 0) ? mb0 : (sl == 1) ? mb1 : mb2;
            mbar_expect_tx(mba, STAGEB);
            bulkcp(sb + sl * STAGEB,         srcA + (size_t)kc * ATILE, ATILE, mba);
            bulkcp(sb + sl * STAGEB + ATILE, srcB + (size_t)kc * BTILE, BTILE, mba);
        }

        uint32_t st = sb + (uint32_t)s * STAGEB;
        #pragma unroll
        for (int half = 0; half < 4; ++half){
            const uint32_t cbyte = cb0 + half * 32;
            uint32_t aF[2][4], bW[4][4];
            #pragma unroll
            for (int im = 0; im < 2; ++im){
                uint32_t row = (uint32_t)(warp_m * 32 + im * 16 + lr);
                ldm4(aF[im], st + swz128(row * 128 + cbyte));
            }
            #pragma unroll
            for (int t = 0; t < 4; ++t){
                uint32_t row = (uint32_t)(warp_n * 64 + t * 16 + lr);
                ldm4(bW[t], st + ATILE + swz128(row * 128 + cbyte));
            }
            #pragma unroll
            for (int im = 0; im < 2; ++im)
                #pragma unroll
                for (int i8 = 0; i8 < 8; ++i8){
                    const int t = i8 >> 1, hf = i8 & 1;
                    mma16816(acc[im][i8], aF[im], bW[t][hf], bW[t][hf + 2]);
                }
        }

        s  = (s  == NSTAGE - 1) ? 0 : s + 1;
        sl = (sl == NSTAGE - 1) ? 0 : sl + 1;
    }

    // epilogue: tanh(y + c) * u, reduce over n, atomic into g_beta
    #pragma unroll
    for (int im = 0; im < 2; ++im){
        #pragma unroll
        for (int rh = 0; rh < 2; ++rh){
            float p = 0.f;
            #pragma unroll
            for (int i8 = 0; i8 < 8; ++i8){
                int n = warp_n * 64 + i8 * 8 + 2 * (lane & 3);
                float v0 = acc[im][i8][rh * 2 + 0];
                float v1 = acc[im][i8][rh * 2 + 1];
                p += fast_tanh(v0 + cs[n])     * us[n];
                p += fast_tanh(v1 + cs[n + 1]) * us[n + 1];
            }
            p += __shfl_xor_sync(0xffffffffu, p, 1);
            p += __shfl_xor_sync(0xffffffffu, p, 2);
            if ((lane & 3) == 0){
                int row = mb * 128 + warp_m * 32 + im * 16 + rh * 8 + (lane >> 2);
                atomicAdd(&g_beta[row], p);
            }
        }
    }
}

// ---------------- kernel C: softmax reductions + zero output ----------------
__global__ void softmax_kernel(float* __restrict__ out){
    __shared__ float red[32];
    const int tid = threadIdx.x;   // 1024 threads
    float mx = -3.0e38f;
    for (int i = tid; i < LL; i += 1024) mx = fmaxf(mx, g_beta[i]);
    #pragma unroll
    for (int o = 16; o; o >>= 1) mx = fmaxf(mx, __shfl_xor_sync(0xffffffffu, mx, o));
    if ((tid & 31) == 0) red[tid >> 5] = mx;
    __syncthreads();
    if (tid < 32){
        float v = red[tid];
        #pragma unroll
        for (int o = 16; o; o >>= 1) v = fmaxf(v, __shfl_xor_sync(0xffffffffu, v, o));
        if (tid == 0) red[0] = v;
    }
    __syncthreads();
    mx = red[0];
    __syncthreads();

    float s = 0.f;
    for (int i = tid; i < LL; i += 1024) s += __expf(g_beta[i] - mx);
    #pragma unroll
    for (int o = 16; o; o >>= 1) s += __shfl_xor_sync(0xffffffffu, s, o);
    if ((tid & 31) == 0) red[tid >> 5] = s;
    __syncthreads();
    if (tid < 32){
        float v = red[tid];
        #pragma unroll
        for (int o = 16; o; o >>= 1) v += __shfl_xor_sync(0xffffffffu, v, o);
        if (tid == 0){ g_red[0] = mx; g_red[1] = v; }
    }
    out[tid] = 0.f;
}

// ---------------- kernel D: s[d] = sum_i alpha_i * h16[i][d] ----------------
// Reads the tiled+swizzled g_hA directly (no row-major mirror needed).
// grid (4 col-quarters, 128 row-blocks), 256 threads.
__global__ __launch_bounds__(256)
void wsum_kernel(float* __restrict__ out){
    __shared__ float wsm[128];
    __shared__ float part[8 * 256];
    __shared__ int alive;
    const int tid = threadIdx.x;
    const int i0 = blockIdx.y * 128;           // aligned to 128-row tiles
    if (tid == 0) alive = 0;
    __syncthreads();

    const float mx = g_red[0];
    const float invZ = 1.0f / g_red[1];
    if (tid < 128){
        float bv = g_beta[i0 + tid] - mx;
        if (bv > -30.f) alive = 1;
        wsm[tid] = __expf(bv) * invZ;
    }
    __syncthreads();
    if (!alive) return;

    const int c  = tid & 31;                   // 8-half chunk within quarter
    const int rg = tid >> 5;                   // row group 0..7
    const int col0 = blockIdx.x * 256 + c * 8; // global column
    const int kc = col0 >> 6;                  // k-chunk 0..15
    const uint32_t jbyte = (uint32_t)((col0 & 63) * 2);  // byte offset in 128B row
    const char* tile = (const char*)g_hA + ((size_t)blockIdx.y * 16 + kc) * 16384;

    float acc[8];
    #pragma unroll
    for (int k = 0; k < 8; ++k) acc[k] = 0.f;

    #pragma unroll 2
    for (int i = rg; i < 128; i += 8){
        uint4 v = *(const uint4*)(tile + swz128((uint32_t)i * 128 + jbyte));
        float w = wsm[i];
        const __half2* h2 = (const __half2*)&v;
        #pragma unroll
        for (int q = 0; q < 4; ++q){
            float2 f = __half22float2(h2[q]);
            acc[2*q + 0] += w * f.x;
            acc[2*q + 1] += w * f.y;
        }
    }
    #pragma unroll
    for (int k = 0; k < 8; ++k) part[rg * 256 + c * 8 + k] = acc[k];
    __syncthreads();

    float sum = 0.f;
    #pragma unroll
    for (int rg2 = 0; rg2 < 8; ++rg2) sum += part[rg2 * 256 + tid];
    atomicAdd(&out[blockIdx.x * 256 + tid], sum);
}

// ---------------- launch ----------------
extern "C" void kernel_launch(void* const* d_in, const int* in_sizes, int n_in,
                              void* d_out, int out_size){
    const float* h_i   = (const float*)d_in[0];
    const float* h_t   = (const float*)d_in[1];
    const float* W_att = (const float*)d_in[2];
    const float* b_att = (const float*)d_in[3];
    const float* u     = (const float*)d_in[4];
    float* out = (float*)d_out;

    cudaFuncSetAttribute(beta_mma_kernel,
                         cudaFuncAttributeMaxDynamicSharedMemorySize, DYN_SMEM);

    prep_kernel<<<8896, 256>>>(h_i, W_att, h_t, b_att);
    beta_mma_kernel<<<dim3(128, 8), 256, DYN_SMEM>>>(u);
    softmax_kernel<<<1, 1024>>>(out);
    wsum_kernel<<<dim3(4, 128), 256>>>(out);
}